// round 6
// baseline (speedup 1.0000x reference)
#include <cuda_runtime.h>

#define NN  100000
#define EE  3200000
#define NB_SCAN 391   // ceil(NN/256)

// ---------------- scratch (static device globals) ---------------------------
__device__ int   g_degi[NN];
__device__ float g_dinv[NN];
__device__ int   g_off[NN + 1];
__device__ int   g_cur[NN];
__device__ int   g_csrc[EE];
__device__ float g_h1s[NN * 32];    // x[n] @ init_w1 (raw), cols = k*16+h
__device__ float g_root1[NN * 32];  // x[n] @ root_w1 (raw)
__device__ float g_hs[NN * 16];     // dinv[n] * h[n]
__device__ float g_aggh[NN * 16];   // dinv[d] * sum_src hs[src]
__device__ int   g_bsum[512];
__device__ int   g_boff[512];

// ---------------- streams/events (created at image load, before harness) ----
struct HxStreams {
    cudaStream_t s2 = nullptr;
    cudaEvent_t ev_fork = nullptr, ev_join = nullptr;
    bool ok = false;
    HxStreams() {
        ok = (cudaStreamCreateWithFlags(&s2, cudaStreamNonBlocking) == cudaSuccess) &&
             (cudaEventCreateWithFlags(&ev_fork, cudaEventDisableTiming) == cudaSuccess) &&
             (cudaEventCreateWithFlags(&ev_join, cudaEventDisableTiming) == cudaSuccess);
    }
};
static HxStreams g_hx;

// ---------------- packed f32x2 helpers ---------------------------------------
typedef unsigned long long u64;
__device__ __forceinline__ u64 ffma2(u64 a, u64 b, u64 c) {
    u64 d;
    asm("fma.rn.f32x2 %0, %1, %2, %3;" : "=l"(d) : "l"(a), "l"(b), "l"(c));
    return d;
}
__device__ __forceinline__ u64 pack2(float lo, float hi) {
    u64 r;
    asm("mov.b64 %0, {%1, %2};" : "=l"(r) : "f"(lo), "f"(hi));
    return r;
}
__device__ __forceinline__ void unpack2(u64 v, float& lo, float& hi) {
    asm("mov.b64 {%0, %1}, %2;" : "=f"(lo), "=f"(hi) : "l"(v));
}

// ---------------- K: zero degree histogram -----------------------------------
__global__ void k_zero() {
    int i = blockIdx.x * blockDim.x + threadIdx.x;
    if (i < NN) g_degi[i] = 0;
}

// ---------------- K: degree histogram (int32 dst, int4 vectorized) ----------
__global__ void k_hist(const int* __restrict__ ei) {
    int e4 = blockIdx.x * blockDim.x + threadIdx.x;
    if (e4 >= EE / 4) return;
    int4 d = *(const int4*)&ei[EE + e4 * 4];
    if ((unsigned)d.x < NN) atomicAdd(&g_degi[d.x], 1);
    if ((unsigned)d.y < NN) atomicAdd(&g_degi[d.y], 1);
    if ((unsigned)d.z < NN) atomicAdd(&g_degi[d.z], 1);
    if ((unsigned)d.w < NN) atomicAdd(&g_degi[d.w], 1);
}

// ---------------- scan partials + dinv ---------------------------------------
__global__ void k_scan_part() {
    __shared__ int sm[256];
    int t = threadIdx.x, b = blockIdx.x;
    int n = b * 256 + t;
    int v = (n < NN) ? g_degi[n] : 0;
    if (n < NN) g_dinv[n] = (v > 0) ? rsqrtf((float)v) : 0.0f;
    sm[t] = v;
    __syncthreads();
    for (int s = 128; s > 0; s >>= 1) {
        if (t < s) sm[t] += sm[t + s];
        __syncthreads();
    }
    if (t == 0) g_bsum[b] = sm[0];
}

__global__ void k_scan_top() {
    __shared__ int sm[512];
    int t = threadIdx.x;
    int v = (t < NB_SCAN) ? g_bsum[t] : 0;
    sm[t] = v;
    __syncthreads();
    for (int d = 1; d < 512; d <<= 1) {
        int x = (t >= d) ? sm[t - d] : 0;
        __syncthreads();
        sm[t] += x;
        __syncthreads();
    }
    if (t < NB_SCAN) g_boff[t] = sm[t] - v;  // exclusive
}

__global__ void k_scan_out() {
    __shared__ int sm[256];
    int t = threadIdx.x, b = blockIdx.x;
    int n = b * 256 + t;
    int v = (n < NN) ? g_degi[n] : 0;
    sm[t] = v;
    __syncthreads();
    for (int d = 1; d < 256; d <<= 1) {
        int x = (t >= d) ? sm[t - d] : 0;
        __syncthreads();
        sm[t] += x;
        __syncthreads();
    }
    int excl = sm[t] - v + g_boff[b];
    if (n < NN) {
        g_off[n] = excl;
        g_cur[n] = excl;
    }
    if (b == 0 && t == 0) g_off[NN] = EE;
}

// ---------------- GEMM1  h1s = x@Wi, root1 = x@Wr (raw, no dinv) ------------
// tile: 128 rows x 64 outs (R4 shape) with R5's zero-MOV inner loop:
// pre-splatted u64 weights in smem + column-major x -> aligned f32x2 pairs.
// thread = 4 row-pairs x 4 cols; per f: 4 LDS.128 + 16 FFMA2, 0 MOV.
#define XPAD 132   // 128 + 4; f*XPAD*4B stays 16B-aligned (132*4=528=33*16)
__global__ void __launch_bounds__(256) k_gemm1(const float* __restrict__ x,
                                               const float* __restrict__ wi,
                                               const float* __restrict__ wr) {
    __shared__ float xs[32 * XPAD];   // column-major: xs[f*XPAD + r]   (~16.9KB)
    __shared__ u64  ws2[32 * 64];     // pre-splatted: both halves = W[f][o] (16KB)
    int tid = threadIdx.x;
    int nb = blockIdx.x * 128;
    int co = tid & 15;   // cols co*4 .. co*4+3
    int rn = tid >> 4;   // rows rn*8 .. rn*8+7 (4 pairs)

    u64 acc[4][4];
#pragma unroll
    for (int p = 0; p < 4; p++)
#pragma unroll
        for (int c = 0; c < 4; c++) acc[p][c] = 0ull;

    for (int fc = 0; fc < 256; fc += 32) {
        // stage x tile [128 rows x 32 f] into column-major xs (4 float4/thr)
#pragma unroll
        for (int j = 0; j < 4; j++) {
            int idx = tid + 256 * j;        // 1024 float4 slots
            int r = idx >> 3;               // row 0..127
            int c4 = (idx & 7) * 4;         // f 0..28
            float4 v = make_float4(0.f, 0.f, 0.f, 0.f);
            int node = nb + r;
            if (node < NN) v = *(const float4*)&x[node * 256 + fc + c4];
            xs[(c4 + 0) * XPAD + r] = v.x;
            xs[(c4 + 1) * XPAD + r] = v.y;
            xs[(c4 + 2) * XPAD + r] = v.z;
            xs[(c4 + 3) * XPAD + r] = v.w;
        }
        // stage pre-splatted W tile [32 f x 64 outs] as u64
        // o layout: [wi k0 h0..15 | wi k1 h0..15 | wr k0 h0..15 | wr k1 h0..15]
#pragma unroll
        for (int j = 0; j < 8; j++) {
            int idx = tid + 256 * j;        // 2048 u64 slots
            int fl = idx >> 6;              // f 0..31
            int o = idx & 63;
            int k = (o >> 4) & 1;
            int h = o & 15;
            const float* wp = (o < 32) ? wi : wr;
            float wv = wp[k * 4096 + (fc + fl) * 16 + h];
            ws2[fl * 64 + o] = pack2(wv, wv);
        }
        __syncthreads();
#pragma unroll 4
        for (int f = 0; f < 32; f++) {
            ulonglong2 wab = *(ulonglong2*)&ws2[f * 64 + co * 4];      // wx, wy
            ulonglong2 wcd = *(ulonglong2*)&ws2[f * 64 + co * 4 + 2];  // wz, ww
            const float* xb = &xs[f * XPAD + rn * 8];
            ulonglong2 x01 = *(ulonglong2*)&xb[0];   // pairs 0,1
            ulonglong2 x23 = *(ulonglong2*)&xb[4];   // pairs 2,3
            u64 xp[4];
            xp[0] = x01.x; xp[1] = x01.y;
            xp[2] = x23.x; xp[3] = x23.y;
#pragma unroll
            for (int p = 0; p < 4; p++) {
                acc[p][0] = ffma2(xp[p], wab.x, acc[p][0]);
                acc[p][1] = ffma2(xp[p], wab.y, acc[p][1]);
                acc[p][2] = ffma2(xp[p], wcd.x, acc[p][2]);
                acc[p][3] = ffma2(xp[p], wcd.y, acc[p][3]);
            }
        }
        __syncthreads();
    }
    // epilogue: pair p holds rows rn*8+2p (lo) and rn*8+2p+1 (hi)
#pragma unroll
    for (int p = 0; p < 4; p++) {
        float4 va, vb;
        unpack2(acc[p][0], va.x, vb.x);
        unpack2(acc[p][1], va.y, vb.y);
        unpack2(acc[p][2], va.z, vb.z);
        unpack2(acc[p][3], va.w, vb.w);
        int ra = nb + rn * 8 + 2 * p;
        int rb = ra + 1;
        if (ra < NN) {
            if (co < 8) *(float4*)&g_h1s[ra * 32 + co * 4] = va;
            else        *(float4*)&g_root1[ra * 32 + (co - 8) * 4] = va;
        }
        if (rb < NN) {
            if (co < 8) *(float4*)&g_h1s[rb * 32 + co * 4] = vb;
            else        *(float4*)&g_root1[rb * 32 + (co - 8) * 4] = vb;
        }
    }
}

// ---------------- CSR scatter (src grouped by dst), int4 vectorized ---------
__global__ void k_csr(const int* __restrict__ ei) {
    int e4 = blockIdx.x * blockDim.x + threadIdx.x;
    if (e4 >= EE / 4) return;
    int4 s = *(const int4*)&ei[e4 * 4];
    int4 d = *(const int4*)&ei[EE + e4 * 4];
    if ((unsigned)d.x < NN) g_csrc[atomicAdd(&g_cur[d.x], 1)] = s.x;
    if ((unsigned)d.y < NN) g_csrc[atomicAdd(&g_cur[d.y], 1)] = s.y;
    if ((unsigned)d.z < NN) g_csrc[atomicAdd(&g_cur[d.z], 1)] = s.z;
    if ((unsigned)d.w < NN) g_csrc[atomicAdd(&g_cur[d.w], 1)] = s.w;
}

// ---------------- layer-1 aggregate + combine (dinv[src] applied here) ------
// warp per dst node; 8 lanes cover one 128B row; 4 neighbors in flight
__global__ void __launch_bounds__(256) k_agg1(const float* __restrict__ bias1,
                                              float* __restrict__ out_agg) {
    int node = blockIdx.x * 8 + (threadIdx.x >> 5);
    int lane = threadIdx.x & 31;
    if (node >= NN) return;
    int beg = g_off[node], end = g_off[node + 1];
    int grp = lane >> 3;       // 0..3: which neighbor in the 4-batch
    int cb = (lane & 7) * 4;   // column base 0..28

    float4 acc = make_float4(0.f, 0.f, 0.f, 0.f);
    for (int t = beg; t < end; t += 32) {
        int idx = t + lane;
        int sv = (idx < end) ? g_csrc[idx] : 0;
        int cnt = min(32, end - t);
        for (int j = 0; j < cnt; j += 4) {
            int jj = j + grp;
            int s = __shfl_sync(0xffffffffu, sv, jj & 31);
            if (jj < cnt) {
                float dvs = g_dinv[s];
                float4 a = *(const float4*)&g_h1s[s * 32 + cb];
                acc.x = fmaf(a.x, dvs, acc.x);
                acc.y = fmaf(a.y, dvs, acc.y);
                acc.z = fmaf(a.z, dvs, acc.z);
                acc.w = fmaf(a.w, dvs, acc.w);
            }
        }
    }
    // reduce across the 4 neighbor groups (lane bits 3,4)
#pragma unroll
    for (int m = 8; m <= 16; m <<= 1) {
        acc.x += __shfl_xor_sync(0xffffffffu, acc.x, m);
        acc.y += __shfl_xor_sync(0xffffffffu, acc.y, m);
        acc.z += __shfl_xor_sync(0xffffffffu, acc.z, m);
        acc.w += __shfl_xor_sync(0xffffffffu, acc.w, m);
    }
    // lanes 0..7 hold full col sums for cols cb..cb+3
    float dv = g_dinv[node];
    float4 root = *(const float4*)&g_root1[node * 32 + cb];
    float4 bv = *(const float4*)&bias1[cb];
    float4 r;
    r.x = fmaxf(dv * acc.x + root.x + bv.x, 0.f);
    r.y = fmaxf(dv * acc.y + root.y + bv.y, 0.f);
    r.z = fmaxf(dv * acc.z + root.z + bv.z, 0.f);
    r.w = fmaxf(dv * acc.w + root.w + bv.w, 0.f);
    // K-mean: col c pairs with c+16 -> lane pairs with lane^4
    float4 o;
    o.x = __shfl_xor_sync(0xffffffffu, r.x, 4);
    o.y = __shfl_xor_sync(0xffffffffu, r.y, 4);
    o.z = __shfl_xor_sync(0xffffffffu, r.z, 4);
    o.w = __shfl_xor_sync(0xffffffffu, r.w, 4);
    float4 h;
    h.x = 0.5f * (r.x + o.x);
    h.y = 0.5f * (r.y + o.y);
    h.z = 0.5f * (r.z + o.z);
    h.w = 0.5f * (r.w + o.w);
    if (lane < 4) {
        *(float4*)&out_agg[node * 16 + lane * 4] = h;   // agg_feature output
        float4 hs = make_float4(h.x * dv, h.y * dv, h.z * dv, h.w * dv);
        *(float4*)&g_hs[node * 16 + lane * 4] = hs;
    }
}

// ---------------- layer-2 aggregate ------------------------------------------
// warp per dst node; 4 lanes cover one 64B row; 8 neighbors in flight
__global__ void __launch_bounds__(256) k_agg2() {
    int node = blockIdx.x * 8 + (threadIdx.x >> 5);
    int lane = threadIdx.x & 31;
    if (node >= NN) return;
    int beg = g_off[node], end = g_off[node + 1];
    int grp = lane >> 2;       // 0..7
    int cb = (lane & 3) * 4;   // column base 0..12

    float4 acc = make_float4(0.f, 0.f, 0.f, 0.f);
    for (int t = beg; t < end; t += 32) {
        int idx = t + lane;
        int sv = (idx < end) ? g_csrc[idx] : 0;
        int cnt = min(32, end - t);
        for (int j = 0; j < cnt; j += 8) {
            int jj = j + grp;
            int s = __shfl_sync(0xffffffffu, sv, jj & 31);
            if (jj < cnt) {
                float4 a = *(const float4*)&g_hs[s * 16 + cb];
                acc.x += a.x; acc.y += a.y; acc.z += a.z; acc.w += a.w;
            }
        }
    }
#pragma unroll
    for (int m = 4; m <= 16; m <<= 1) {
        acc.x += __shfl_xor_sync(0xffffffffu, acc.x, m);
        acc.y += __shfl_xor_sync(0xffffffffu, acc.y, m);
        acc.z += __shfl_xor_sync(0xffffffffu, acc.z, m);
        acc.w += __shfl_xor_sync(0xffffffffu, acc.w, m);
    }
    if (lane < 4) {
        float dv = g_dinv[node];
        float4 v = make_float4(acc.x * dv, acc.y * dv, acc.z * dv, acc.w * dv);
        *(float4*)&g_aggh[node * 16 + lane * 4] = v;
    }
}

// ---------------- layer-2 transform + log_softmax ----------------------------
__global__ void __launch_bounds__(256) k_final(const float* __restrict__ wi2,
                                               const float* __restrict__ wr2,
                                               const float* __restrict__ b2,
                                               const float* __restrict__ hsrc,
                                               float* __restrict__ out_logits) {
    __shared__ float Wi[256], Wr[256], Ba[16];
    int t = threadIdx.x;
    // K-mean commutes with identity activation -> average weights over stacks
    Wi[t] = 0.5f * (wi2[t] + wi2[256 + t]);
    Wr[t] = 0.5f * (wr2[t] + wr2[256 + t]);
    if (t < 16) Ba[t] = 0.5f * (b2[t] + b2[16 + t]);
    __syncthreads();

    int n = blockIdx.x * 256 + t;
    if (n >= NN) return;
    float g[16], h[16];
#pragma unroll
    for (int j = 0; j < 4; j++) {
        float4 gv = *(const float4*)&g_aggh[n * 16 + j * 4];
        float4 hv = *(const float4*)&hsrc[n * 16 + j * 4];
        g[j * 4 + 0] = gv.x; g[j * 4 + 1] = gv.y; g[j * 4 + 2] = gv.z; g[j * 4 + 3] = gv.w;
        h[j * 4 + 0] = hv.x; h[j * 4 + 1] = hv.y; h[j * 4 + 2] = hv.z; h[j * 4 + 3] = hv.w;
    }
    float l[16];
    float m = -1e30f;
#pragma unroll
    for (int o = 0; o < 16; o++) {
        float a = Ba[o];
#pragma unroll
        for (int ff = 0; ff < 16; ff++)
            a += g[ff] * Wi[ff * 16 + o] + h[ff] * Wr[ff * 16 + o];
        l[o] = a;
        m = fmaxf(m, a);
    }
    float s = 0.f;
#pragma unroll
    for (int o = 0; o < 16; o++) s += expf(l[o] - m);
    float ls = logf(s);
#pragma unroll
    for (int j = 0; j < 4; j++) {
        float4 v;
        v.x = l[j * 4 + 0] - m - ls;
        v.y = l[j * 4 + 1] - m - ls;
        v.z = l[j * 4 + 2] - m - ls;
        v.w = l[j * 4 + 3] - m - ls;
        *(float4*)&out_logits[n * 16 + j * 4] = v;
    }
}

// ---------------- launch -----------------------------------------------------
extern "C" void kernel_launch(void* const* d_in, const int* in_sizes, int n_in,
                              void* d_out, int out_size) {
    const float* x   = (const float*)d_in[0];
    const int*   ei  = (const int*)d_in[1];     // int32 (JAX x64 disabled)
    const float* wi1 = (const float*)d_in[2];
    const float* wr1 = (const float*)d_in[3];
    const float* b1  = (const float*)d_in[4];
    const float* wi2 = (const float*)d_in[5];
    const float* wr2 = (const float*)d_in[6];
    const float* b2  = (const float*)d_in[7];
    float* out        = (float*)d_out;
    float* out_logits = out;            // [N, 16] log_softmax
    float* out_agg    = out + NN * 16;  // [N, 16] agg_feature

    bool dual = g_hx.ok;
    if (dual) cudaEventRecord(g_hx.ev_fork, 0);   // fork point

    // main stream: CSR build chain
    k_zero<<<(NN + 255) / 256, 256>>>();
    k_hist<<<(EE / 4 + 255) / 256, 256>>>(ei);
    k_scan_part<<<NB_SCAN, 256>>>();

    // gemm1: independent of everything; overlaps the CSR chain on s2
    if (dual) {
        cudaStreamWaitEvent(g_hx.s2, g_hx.ev_fork, 0);
        k_gemm1<<<(NN + 127) / 128, 256, 0, g_hx.s2>>>(x, wi1, wr1);  // 4th launch
        cudaEventRecord(g_hx.ev_join, g_hx.s2);
    } else {
        k_gemm1<<<(NN + 127) / 128, 256>>>(x, wi1, wr1);
    }

    k_scan_top<<<1, 512>>>();
    k_scan_out<<<NB_SCAN, 256>>>();
    k_csr<<<(EE / 4 + 255) / 256, 256>>>(ei);

    if (dual) cudaStreamWaitEvent(0, g_hx.ev_join, 0);  // join before agg1

    k_agg1<<<(NN + 7) / 8, 256>>>(b1, out_agg);
    k_agg2<<<(NN + 7) / 8, 256>>>();
    k_final<<<(NN + 255) / 256, 256>>>(wi2, wr2, b2, out_agg, out_logits);
}

// round 7
// speedup vs baseline: 1.1265x; 1.1265x over previous
#include <cuda_runtime.h>

#define NN  100000
#define EE  3200000
#define NB_SCAN 391   // ceil(NN/256)

// ---------------- scratch (static device globals) ---------------------------
__device__ int   g_degi[NN];
__device__ float g_dinv[NN];
__device__ int   g_off[NN + 1];
__device__ int   g_cur[NN];
__device__ int   g_csrc[EE];
__device__ float g_h1s[NN * 32];    // x[n] @ init_w1 (raw), cols = k*16+h
__device__ float g_root1[NN * 32];  // x[n] @ root_w1 (raw)
__device__ float g_hs[NN * 16];     // dinv[n] * h[n]
__device__ float g_aggh[NN * 16];   // dinv[d] * sum_src hs[src]
__device__ int   g_bsum[512];
__device__ int   g_boff[512];

// ---------------- streams/events (created at image load, before harness) ----
struct HxStreams {
    cudaStream_t s2 = nullptr;
    cudaEvent_t ev_fork = nullptr, ev_join = nullptr;
    bool ok = false;
    HxStreams() {
        ok = (cudaStreamCreateWithFlags(&s2, cudaStreamNonBlocking) == cudaSuccess) &&
             (cudaEventCreateWithFlags(&ev_fork, cudaEventDisableTiming) == cudaSuccess) &&
             (cudaEventCreateWithFlags(&ev_join, cudaEventDisableTiming) == cudaSuccess);
    }
};
static HxStreams g_hx;

// ---------------- packed f32x2 helpers ---------------------------------------
typedef unsigned long long u64;
__device__ __forceinline__ u64 ffma2(u64 a, u64 b, u64 c) {
    u64 d;
    asm("fma.rn.f32x2 %0, %1, %2, %3;" : "=l"(d) : "l"(a), "l"(b), "l"(c));
    return d;
}
__device__ __forceinline__ u64 pack2(float lo, float hi) {
    u64 r;
    asm("mov.b64 %0, {%1, %2};" : "=l"(r) : "f"(lo), "f"(hi));
    return r;
}
__device__ __forceinline__ void unpack2(u64 v, float& lo, float& hi) {
    asm("mov.b64 {%0, %1}, %2;" : "=f"(lo), "=f"(hi) : "l"(v));
}

// ---------------- K: zero degree histogram -----------------------------------
__global__ void k_zero() {
    int i = blockIdx.x * blockDim.x + threadIdx.x;
    if (i < NN) g_degi[i] = 0;
}

// ---------------- K: degree histogram (int32 dst, int4 vectorized) ----------
__global__ void k_hist(const int* __restrict__ ei) {
    int e4 = blockIdx.x * blockDim.x + threadIdx.x;
    if (e4 >= EE / 4) return;
    int4 d = *(const int4*)&ei[EE + e4 * 4];
    if ((unsigned)d.x < NN) atomicAdd(&g_degi[d.x], 1);
    if ((unsigned)d.y < NN) atomicAdd(&g_degi[d.y], 1);
    if ((unsigned)d.z < NN) atomicAdd(&g_degi[d.z], 1);
    if ((unsigned)d.w < NN) atomicAdd(&g_degi[d.w], 1);
}

// ---------------- scan partials + dinv ---------------------------------------
__global__ void k_scan_part() {
    __shared__ int sm[256];
    int t = threadIdx.x, b = blockIdx.x;
    int n = b * 256 + t;
    int v = (n < NN) ? g_degi[n] : 0;
    if (n < NN) g_dinv[n] = (v > 0) ? rsqrtf((float)v) : 0.0f;
    sm[t] = v;
    __syncthreads();
    for (int s = 128; s > 0; s >>= 1) {
        if (t < s) sm[t] += sm[t + s];
        __syncthreads();
    }
    if (t == 0) g_bsum[b] = sm[0];
}

__global__ void k_scan_top() {
    __shared__ int sm[512];
    int t = threadIdx.x;
    int v = (t < NB_SCAN) ? g_bsum[t] : 0;
    sm[t] = v;
    __syncthreads();
    for (int d = 1; d < 512; d <<= 1) {
        int x = (t >= d) ? sm[t - d] : 0;
        __syncthreads();
        sm[t] += x;
        __syncthreads();
    }
    if (t < NB_SCAN) g_boff[t] = sm[t] - v;  // exclusive
}

__global__ void k_scan_out() {
    __shared__ int sm[256];
    int t = threadIdx.x, b = blockIdx.x;
    int n = b * 256 + t;
    int v = (n < NN) ? g_degi[n] : 0;
    sm[t] = v;
    __syncthreads();
    for (int d = 1; d < 256; d <<= 1) {
        int x = (t >= d) ? sm[t - d] : 0;
        __syncthreads();
        sm[t] += x;
        __syncthreads();
    }
    int excl = sm[t] - v + g_boff[b];
    if (n < NN) {
        g_off[n] = excl;
        g_cur[n] = excl;
    }
    if (b == 0 && t == 0) g_off[NN] = EE;
}

// ---------------- GEMM1  h1s = x@Wi, root1 = x@Wr (raw, no dinv) ------------
// tile: 128 rows x 64 outs; thread = 4 row-pairs x 4 cols via FFMA2.
// Per f: 1 LDS.128 (natural w float4, 2 wf) + 2 LDS.128 (x pairs, broadcast,
// 2 wf) + 4 reg splats + 16 FFMA2 -> FFMA2-bound (others < FFMA2 count).
#define XPAD 132   // 128 + 4; f*XPAD*4B stays 16B-aligned (132*4=528=33*16)
__global__ void __launch_bounds__(256) k_gemm1(const float* __restrict__ x,
                                               const float* __restrict__ wi,
                                               const float* __restrict__ wr) {
    __shared__ float xs[32 * XPAD];   // column-major: xs[f*XPAD + r]  (~16.9KB)
    __shared__ float ws[32 * 64];     // natural floats: ws[f*64 + o]  (8KB)
    int tid = threadIdx.x;
    int nb = blockIdx.x * 128;
    int co = tid & 15;   // cols co*4 .. co*4+3
    int rn = tid >> 4;   // rows rn*8 .. rn*8+7 (4 pairs)

    u64 acc[4][4];
#pragma unroll
    for (int p = 0; p < 4; p++)
#pragma unroll
        for (int c = 0; c < 4; c++) acc[p][c] = 0ull;

    for (int fc = 0; fc < 256; fc += 32) {
        // stage x tile [128 rows x 32 f] into column-major xs (4 float4/thr)
#pragma unroll
        for (int j = 0; j < 4; j++) {
            int idx = tid + 256 * j;        // 1024 float4 slots
            int r = idx >> 3;               // row 0..127
            int c4 = (idx & 7) * 4;         // f 0..28
            float4 v = make_float4(0.f, 0.f, 0.f, 0.f);
            int node = nb + r;
            if (node < NN) v = *(const float4*)&x[node * 256 + fc + c4];
            xs[(c4 + 0) * XPAD + r] = v.x;
            xs[(c4 + 1) * XPAD + r] = v.y;
            xs[(c4 + 2) * XPAD + r] = v.z;
            xs[(c4 + 3) * XPAD + r] = v.w;
        }
        // stage natural W tile [32 f x 64 outs], 2 float4/thread
        // o layout: [wi k0 h0..15 | wi k1 h0..15 | wr k0 h0..15 | wr k1 h0..15]
#pragma unroll
        for (int j = 0; j < 2; j++) {
            int idx = tid + 256 * j;        // 512 float4 slots
            int fl = idx >> 4;              // f 0..31
            int o4 = idx & 15;
            int m = o4 >> 2;                // 0..3
            int k = m & 1;
            int h4 = o4 & 3;
            const float* wp = (m < 2) ? wi : wr;
            float4 v = *(const float4*)&wp[k * 4096 + (fc + fl) * 16 + h4 * 4];
            *(float4*)&ws[fl * 64 + o4 * 4] = v;
        }
        __syncthreads();
#pragma unroll 4
        for (int f = 0; f < 32; f++) {
            float4 w = *(float4*)&ws[f * 64 + co * 4];
            u64 wx = pack2(w.x, w.x);
            u64 wy = pack2(w.y, w.y);
            u64 wz = pack2(w.z, w.z);
            u64 wwv = pack2(w.w, w.w);
            const float* xb = &xs[f * XPAD + rn * 8];
            ulonglong2 x01 = *(ulonglong2*)&xb[0];   // row-pairs 0,1
            ulonglong2 x23 = *(ulonglong2*)&xb[4];   // row-pairs 2,3
            u64 xp[4];
            xp[0] = x01.x; xp[1] = x01.y;
            xp[2] = x23.x; xp[3] = x23.y;
#pragma unroll
            for (int p = 0; p < 4; p++) {
                acc[p][0] = ffma2(xp[p], wx, acc[p][0]);
                acc[p][1] = ffma2(xp[p], wy, acc[p][1]);
                acc[p][2] = ffma2(xp[p], wz, acc[p][2]);
                acc[p][3] = ffma2(xp[p], wwv, acc[p][3]);
            }
        }
        __syncthreads();
    }
    // epilogue: pair p holds rows rn*8+2p (lo) and rn*8+2p+1 (hi)
#pragma unroll
    for (int p = 0; p < 4; p++) {
        float4 va, vb;
        unpack2(acc[p][0], va.x, vb.x);
        unpack2(acc[p][1], va.y, vb.y);
        unpack2(acc[p][2], va.z, vb.z);
        unpack2(acc[p][3], va.w, vb.w);
        int ra = nb + rn * 8 + 2 * p;
        int rb = ra + 1;
        if (ra < NN) {
            if (co < 8) *(float4*)&g_h1s[ra * 32 + co * 4] = va;
            else        *(float4*)&g_root1[ra * 32 + (co - 8) * 4] = va;
        }
        if (rb < NN) {
            if (co < 8) *(float4*)&g_h1s[rb * 32 + co * 4] = vb;
            else        *(float4*)&g_root1[rb * 32 + (co - 8) * 4] = vb;
        }
    }
}

// ---------------- CSR scatter (src grouped by dst), int4 vectorized ---------
__global__ void k_csr(const int* __restrict__ ei) {
    int e4 = blockIdx.x * blockDim.x + threadIdx.x;
    if (e4 >= EE / 4) return;
    int4 s = *(const int4*)&ei[e4 * 4];
    int4 d = *(const int4*)&ei[EE + e4 * 4];
    if ((unsigned)d.x < NN) g_csrc[atomicAdd(&g_cur[d.x], 1)] = s.x;
    if ((unsigned)d.y < NN) g_csrc[atomicAdd(&g_cur[d.y], 1)] = s.y;
    if ((unsigned)d.z < NN) g_csrc[atomicAdd(&g_cur[d.z], 1)] = s.z;
    if ((unsigned)d.w < NN) g_csrc[atomicAdd(&g_cur[d.w], 1)] = s.w;
}

// ---------------- layer-1 aggregate + combine (dinv[src] applied here) ------
// warp per dst node; 8 lanes cover one 128B row; 4 neighbors in flight
__global__ void __launch_bounds__(256) k_agg1(const float* __restrict__ bias1,
                                              float* __restrict__ out_agg) {
    int node = blockIdx.x * 8 + (threadIdx.x >> 5);
    int lane = threadIdx.x & 31;
    if (node >= NN) return;
    int beg = g_off[node], end = g_off[node + 1];
    int grp = lane >> 3;       // 0..3: which neighbor in the 4-batch
    int cb = (lane & 7) * 4;   // column base 0..28

    float4 acc = make_float4(0.f, 0.f, 0.f, 0.f);
    for (int t = beg; t < end; t += 32) {
        int idx = t + lane;
        int sv = (idx < end) ? g_csrc[idx] : 0;
        int cnt = min(32, end - t);
        for (int j = 0; j < cnt; j += 4) {
            int jj = j + grp;
            int s = __shfl_sync(0xffffffffu, sv, jj & 31);
            if (jj < cnt) {
                float dvs = g_dinv[s];
                float4 a = *(const float4*)&g_h1s[s * 32 + cb];
                acc.x = fmaf(a.x, dvs, acc.x);
                acc.y = fmaf(a.y, dvs, acc.y);
                acc.z = fmaf(a.z, dvs, acc.z);
                acc.w = fmaf(a.w, dvs, acc.w);
            }
        }
    }
    // reduce across the 4 neighbor groups (lane bits 3,4)
#pragma unroll
    for (int m = 8; m <= 16; m <<= 1) {
        acc.x += __shfl_xor_sync(0xffffffffu, acc.x, m);
        acc.y += __shfl_xor_sync(0xffffffffu, acc.y, m);
        acc.z += __shfl_xor_sync(0xffffffffu, acc.z, m);
        acc.w += __shfl_xor_sync(0xffffffffu, acc.w, m);
    }
    // lanes 0..7 hold full col sums for cols cb..cb+3
    float dv = g_dinv[node];
    float4 root = *(const float4*)&g_root1[node * 32 + cb];
    float4 bv = *(const float4*)&bias1[cb];
    float4 r;
    r.x = fmaxf(dv * acc.x + root.x + bv.x, 0.f);
    r.y = fmaxf(dv * acc.y + root.y + bv.y, 0.f);
    r.z = fmaxf(dv * acc.z + root.z + bv.z, 0.f);
    r.w = fmaxf(dv * acc.w + root.w + bv.w, 0.f);
    // K-mean: col c pairs with c+16 -> lane pairs with lane^4
    float4 o;
    o.x = __shfl_xor_sync(0xffffffffu, r.x, 4);
    o.y = __shfl_xor_sync(0xffffffffu, r.y, 4);
    o.z = __shfl_xor_sync(0xffffffffu, r.z, 4);
    o.w = __shfl_xor_sync(0xffffffffu, r.w, 4);
    float4 h;
    h.x = 0.5f * (r.x + o.x);
    h.y = 0.5f * (r.y + o.y);
    h.z = 0.5f * (r.z + o.z);
    h.w = 0.5f * (r.w + o.w);
    if (lane < 4) {
        *(float4*)&out_agg[node * 16 + lane * 4] = h;   // agg_feature output
        float4 hs = make_float4(h.x * dv, h.y * dv, h.z * dv, h.w * dv);
        *(float4*)&g_hs[node * 16 + lane * 4] = hs;
    }
}

// ---------------- layer-2 aggregate ------------------------------------------
// warp per dst node; 4 lanes cover one 64B row; 8 neighbors in flight
__global__ void __launch_bounds__(256) k_agg2() {
    int node = blockIdx.x * 8 + (threadIdx.x >> 5);
    int lane = threadIdx.x & 31;
    if (node >= NN) return;
    int beg = g_off[node], end = g_off[node + 1];
    int grp = lane >> 2;       // 0..7
    int cb = (lane & 3) * 4;   // column base 0..12

    float4 acc = make_float4(0.f, 0.f, 0.f, 0.f);
    for (int t = beg; t < end; t += 32) {
        int idx = t + lane;
        int sv = (idx < end) ? g_csrc[idx] : 0;
        int cnt = min(32, end - t);
        for (int j = 0; j < cnt; j += 8) {
            int jj = j + grp;
            int s = __shfl_sync(0xffffffffu, sv, jj & 31);
            if (jj < cnt) {
                float4 a = *(const float4*)&g_hs[s * 16 + cb];
                acc.x += a.x; acc.y += a.y; acc.z += a.z; acc.w += a.w;
            }
        }
    }
#pragma unroll
    for (int m = 4; m <= 16; m <<= 1) {
        acc.x += __shfl_xor_sync(0xffffffffu, acc.x, m);
        acc.y += __shfl_xor_sync(0xffffffffu, acc.y, m);
        acc.z += __shfl_xor_sync(0xffffffffu, acc.z, m);
        acc.w += __shfl_xor_sync(0xffffffffu, acc.w, m);
    }
    if (lane < 4) {
        float dv = g_dinv[node];
        float4 v = make_float4(acc.x * dv, acc.y * dv, acc.z * dv, acc.w * dv);
        *(float4*)&g_aggh[node * 16 + lane * 4] = v;
    }
}

// ---------------- layer-2 transform + log_softmax ----------------------------
__global__ void __launch_bounds__(256) k_final(const float* __restrict__ wi2,
                                               const float* __restrict__ wr2,
                                               const float* __restrict__ b2,
                                               const float* __restrict__ hsrc,
                                               float* __restrict__ out_logits) {
    __shared__ float Wi[256], Wr[256], Ba[16];
    int t = threadIdx.x;
    // K-mean commutes with identity activation -> average weights over stacks
    Wi[t] = 0.5f * (wi2[t] + wi2[256 + t]);
    Wr[t] = 0.5f * (wr2[t] + wr2[256 + t]);
    if (t < 16) Ba[t] = 0.5f * (b2[t] + b2[16 + t]);
    __syncthreads();

    int n = blockIdx.x * 256 + t;
    if (n >= NN) return;
    float g[16], h[16];
#pragma unroll
    for (int j = 0; j < 4; j++) {
        float4 gv = *(const float4*)&g_aggh[n * 16 + j * 4];
        float4 hv = *(const float4*)&hsrc[n * 16 + j * 4];
        g[j * 4 + 0] = gv.x; g[j * 4 + 1] = gv.y; g[j * 4 + 2] = gv.z; g[j * 4 + 3] = gv.w;
        h[j * 4 + 0] = hv.x; h[j * 4 + 1] = hv.y; h[j * 4 + 2] = hv.z; h[j * 4 + 3] = hv.w;
    }
    float l[16];
    float m = -1e30f;
#pragma unroll
    for (int o = 0; o < 16; o++) {
        float a = Ba[o];
#pragma unroll
        for (int ff = 0; ff < 16; ff++)
            a += g[ff] * Wi[ff * 16 + o] + h[ff] * Wr[ff * 16 + o];
        l[o] = a;
        m = fmaxf(m, a);
    }
    float s = 0.f;
#pragma unroll
    for (int o = 0; o < 16; o++) s += expf(l[o] - m);
    float ls = logf(s);
#pragma unroll
    for (int j = 0; j < 4; j++) {
        float4 v;
        v.x = l[j * 4 + 0] - m - ls;
        v.y = l[j * 4 + 1] - m - ls;
        v.z = l[j * 4 + 2] - m - ls;
        v.w = l[j * 4 + 3] - m - ls;
        *(float4*)&out_logits[n * 16 + j * 4] = v;
    }
}

// ---------------- launch -----------------------------------------------------
extern "C" void kernel_launch(void* const* d_in, const int* in_sizes, int n_in,
                              void* d_out, int out_size) {
    const float* x   = (const float*)d_in[0];
    const int*   ei  = (const int*)d_in[1];     // int32 (JAX x64 disabled)
    const float* wi1 = (const float*)d_in[2];
    const float* wr1 = (const float*)d_in[3];
    const float* b1  = (const float*)d_in[4];
    const float* wi2 = (const float*)d_in[5];
    const float* wr2 = (const float*)d_in[6];
    const float* b2  = (const float*)d_in[7];
    float* out        = (float*)d_out;
    float* out_logits = out;            // [N, 16] log_softmax
    float* out_agg    = out + NN * 16;  // [N, 16] agg_feature

    bool dual = g_hx.ok;
    if (dual) cudaEventRecord(g_hx.ev_fork, 0);   // fork point

    // main stream: CSR build chain
    k_zero<<<(NN + 255) / 256, 256>>>();
    k_hist<<<(EE / 4 + 255) / 256, 256>>>(ei);
    k_scan_part<<<NB_SCAN, 256>>>();

    // gemm1: independent of everything; overlaps the CSR chain on s2
    if (dual) {
        cudaStreamWaitEvent(g_hx.s2, g_hx.ev_fork, 0);
        k_gemm1<<<(NN + 127) / 128, 256, 0, g_hx.s2>>>(x, wi1, wr1);
        cudaEventRecord(g_hx.ev_join, g_hx.s2);
    } else {
        k_gemm1<<<(NN + 127) / 128, 256>>>(x, wi1, wr1);
    }

    k_scan_top<<<1, 512>>>();
    k_scan_out<<<NB_SCAN, 256>>>();
    k_csr<<<(EE / 4 + 255) / 256, 256>>>(ei);

    if (dual) cudaStreamWaitEvent(0, g_hx.ev_join, 0);  // join before agg1

    k_agg1<<<(NN + 7) / 8, 256>>>(b1, out_agg);
    k_agg2<<<(NN + 7) / 8, 256>>>();
    k_final<<<(NN + 255) / 256, 256>>>(wi2, wr2, b2, out_agg, out_logits);
}

// round 8
// speedup vs baseline: 1.2239x; 1.0864x over previous
#include <cuda_runtime.h>

#define NN  100000
#define EE  3200000
#define NB_SCAN 391   // ceil(NN/256)

// ---------------- scratch (static device globals) ---------------------------
__device__ int   g_degi[NN];
__device__ float g_dinv[NN];
__device__ int   g_off[NN + 1];
__device__ int   g_cur[NN];
__device__ int   g_csrc[EE];
__device__ float g_h1s[NN * 32];    // x@init_w1; after k_scale: dinv[n]*that
__device__ float g_root1[NN * 32];  // x[n] @ root_w1 (raw)
__device__ float g_hs[NN * 16];     // dinv[n] * h[n]
__device__ float g_aggh[NN * 16];   // dinv[d] * sum_src hs[src]
__device__ int   g_bsum[512];
__device__ int   g_boff[512];

// ---------------- streams/events (created at image load, before harness) ----
struct HxStreams {
    cudaStream_t s2 = nullptr;
    cudaEvent_t ev_fork = nullptr, ev_dinv = nullptr, ev_join = nullptr;
    bool ok = false;
    HxStreams() {
        ok = (cudaStreamCreateWithFlags(&s2, cudaStreamNonBlocking) == cudaSuccess) &&
             (cudaEventCreateWithFlags(&ev_fork, cudaEventDisableTiming) == cudaSuccess) &&
             (cudaEventCreateWithFlags(&ev_dinv, cudaEventDisableTiming) == cudaSuccess) &&
             (cudaEventCreateWithFlags(&ev_join, cudaEventDisableTiming) == cudaSuccess);
    }
};
static HxStreams g_hx;

// ---------------- packed f32x2 helpers ---------------------------------------
typedef unsigned long long u64;
__device__ __forceinline__ u64 ffma2(u64 a, u64 b, u64 c) {
    u64 d;
    asm("fma.rn.f32x2 %0, %1, %2, %3;" : "=l"(d) : "l"(a), "l"(b), "l"(c));
    return d;
}
__device__ __forceinline__ u64 pack2(float lo, float hi) {
    u64 r;
    asm("mov.b64 %0, {%1, %2};" : "=l"(r) : "f"(lo), "f"(hi));
    return r;
}
__device__ __forceinline__ void unpack2(u64 v, float& lo, float& hi) {
    asm("mov.b64 {%0, %1}, %2;" : "=f"(lo), "=f"(hi) : "l"(v));
}

// ---------------- K: zero degree histogram -----------------------------------
__global__ void k_zero() {
    int i = blockIdx.x * blockDim.x + threadIdx.x;
    if (i < NN) g_degi[i] = 0;
}

// ---------------- K: degree histogram (int32 dst, int4 vectorized) ----------
__global__ void k_hist(const int* __restrict__ ei) {
    int e4 = blockIdx.x * blockDim.x + threadIdx.x;
    if (e4 >= EE / 4) return;
    int4 d = *(const int4*)&ei[EE + e4 * 4];
    if ((unsigned)d.x < NN) atomicAdd(&g_degi[d.x], 1);
    if ((unsigned)d.y < NN) atomicAdd(&g_degi[d.y], 1);
    if ((unsigned)d.z < NN) atomicAdd(&g_degi[d.z], 1);
    if ((unsigned)d.w < NN) atomicAdd(&g_degi[d.w], 1);
}

// ---------------- scan partials + dinv ---------------------------------------
__global__ void k_scan_part() {
    __shared__ int sm[256];
    int t = threadIdx.x, b = blockIdx.x;
    int n = b * 256 + t;
    int v = (n < NN) ? g_degi[n] : 0;
    if (n < NN) g_dinv[n] = (v > 0) ? rsqrtf((float)v) : 0.0f;
    sm[t] = v;
    __syncthreads();
    for (int s = 128; s > 0; s >>= 1) {
        if (t < s) sm[t] += sm[t + s];
        __syncthreads();
    }
    if (t == 0) g_bsum[b] = sm[0];
}

__global__ void k_scan_top() {
    __shared__ int sm[512];
    int t = threadIdx.x;
    int v = (t < NB_SCAN) ? g_bsum[t] : 0;
    sm[t] = v;
    __syncthreads();
    for (int d = 1; d < 512; d <<= 1) {
        int x = (t >= d) ? sm[t - d] : 0;
        __syncthreads();
        sm[t] += x;
        __syncthreads();
    }
    if (t < NB_SCAN) g_boff[t] = sm[t] - v;  // exclusive
}

__global__ void k_scan_out() {
    __shared__ int sm[256];
    int t = threadIdx.x, b = blockIdx.x;
    int n = b * 256 + t;
    int v = (n < NN) ? g_degi[n] : 0;
    sm[t] = v;
    __syncthreads();
    for (int d = 1; d < 256; d <<= 1) {
        int x = (t >= d) ? sm[t - d] : 0;
        __syncthreads();
        sm[t] += x;
        __syncthreads();
    }
    int excl = sm[t] - v + g_boff[b];
    if (n < NN) {
        g_off[n] = excl;
        g_cur[n] = excl;
    }
    if (b == 0 && t == 0) g_off[NN] = EE;
}

// ---------------- GEMM1 (R4 champion variant, 86.4us measured) ---------------
// tile: 128 nodes x 64 outputs, 256 threads; thread = 8 rows x 4 cols (f32x2)
__global__ void __launch_bounds__(256) k_gemm1(const float* __restrict__ x,
                                               const float* __restrict__ wi,
                                               const float* __restrict__ wr) {
    __shared__ float xs[128 * 68];
    __shared__ float ws[64 * 64];
    int tid = threadIdx.x;
    int nb = blockIdx.x * 128;
    int co = tid & 15;   // output group: cols co*4 .. co*4+3
    int rn = tid >> 4;   // row group:    rows rn*8 .. rn*8+7

    u64 acc[8][2];
#pragma unroll
    for (int i = 0; i < 8; i++) { acc[i][0] = 0ull; acc[i][1] = 0ull; }

    for (int fc = 0; fc < 256; fc += 64) {
        // stage x tile [128 rows x 64 features], 8 float4/thread
#pragma unroll
        for (int j = 0; j < 8; j++) {
            int idx = tid + 256 * j;
            int r = idx >> 4;
            int c4 = (idx & 15) * 4;
            float4 v = make_float4(0.f, 0.f, 0.f, 0.f);
            int node = nb + r;
            if (node < NN) v = *(const float4*)&x[node * 256 + fc + c4];
            *(float4*)&xs[r * 68 + c4] = v;
        }
        // stage W tile [64 f x 64 outputs], 4 float4/thread
        // o layout: [wi k0 h0..15 | wi k1 h0..15 | wr k0 h0..15 | wr k1 h0..15]
#pragma unroll
        for (int j = 0; j < 4; j++) {
            int idx = tid + 256 * j;
            int fl = idx >> 4;
            int o4 = idx & 15;
            int m = o4 >> 2;      // 0..3
            int k = m & 1;
            int h4 = o4 & 3;
            const float* wp = (m < 2) ? wi : wr;
            float4 v = *(const float4*)&wp[k * 4096 + (fc + fl) * 16 + h4 * 4];
            *(float4*)&ws[fl * 64 + o4 * 4] = v;
        }
        __syncthreads();
#pragma unroll 8
        for (int f = 0; f < 64; f++) {
            float4 w = *(float4*)&ws[f * 64 + co * 4];
            u64 w01 = pack2(w.x, w.y);
            u64 w23 = pack2(w.z, w.w);
#pragma unroll
            for (int i = 0; i < 8; i++) {
                float xv = xs[(rn * 8 + i) * 68 + f];
                u64 xx = pack2(xv, xv);
                acc[i][0] = ffma2(xx, w01, acc[i][0]);
                acc[i][1] = ffma2(xx, w23, acc[i][1]);
            }
        }
        __syncthreads();
    }
    // epilogue (raw outputs; dinv applied later by k_scale)
#pragma unroll
    for (int i = 0; i < 8; i++) {
        int node = nb + rn * 8 + i;
        if (node >= NN) continue;
        float4 v;
        unpack2(acc[i][0], v.x, v.y);
        unpack2(acc[i][1], v.z, v.w);
        if (co < 8) {
            *(float4*)&g_h1s[node * 32 + co * 4] = v;
        } else {
            *(float4*)&g_root1[node * 32 + (co - 8) * 4] = v;
        }
    }
}

// ---------------- K: scale h1s rows by dinv (streaming, ~4us) ---------------
__global__ void k_scale() {
    int i = blockIdx.x * blockDim.x + threadIdx.x;   // over NN*8 float4s
    if (i >= NN * 8) return;
    int node = i >> 3;
    float dv = g_dinv[node];
    float4 v = *(float4*)&g_h1s[i * 4];
    v.x *= dv; v.y *= dv; v.z *= dv; v.w *= dv;
    *(float4*)&g_h1s[i * 4] = v;
}

// ---------------- CSR scatter (src grouped by dst), int4 vectorized ---------
__global__ void k_csr(const int* __restrict__ ei) {
    int e4 = blockIdx.x * blockDim.x + threadIdx.x;
    if (e4 >= EE / 4) return;
    int4 s = *(const int4*)&ei[e4 * 4];
    int4 d = *(const int4*)&ei[EE + e4 * 4];
    if ((unsigned)d.x < NN) g_csrc[atomicAdd(&g_cur[d.x], 1)] = s.x;
    if ((unsigned)d.y < NN) g_csrc[atomicAdd(&g_cur[d.y], 1)] = s.y;
    if ((unsigned)d.z < NN) g_csrc[atomicAdd(&g_cur[d.z], 1)] = s.z;
    if ((unsigned)d.w < NN) g_csrc[atomicAdd(&g_cur[d.w], 1)] = s.w;
}

// ---------------- layer-1 aggregate + combine --------------------------------
// warp per dst node; 8 lanes cover one 128B row; 4 neighbors in flight.
// h1s rows are pre-scaled by dinv[src] (k_scale) -> pure add-gather.
__global__ void __launch_bounds__(256) k_agg1(const float* __restrict__ bias1,
                                              float* __restrict__ out_agg) {
    int node = blockIdx.x * 8 + (threadIdx.x >> 5);
    int lane = threadIdx.x & 31;
    if (node >= NN) return;
    int beg = g_off[node], end = g_off[node + 1];
    int grp = lane >> 3;       // 0..3: which neighbor in the 4-batch
    int cb = (lane & 7) * 4;   // column base 0..28

    float4 acc = make_float4(0.f, 0.f, 0.f, 0.f);
    for (int t = beg; t < end; t += 32) {
        int idx = t + lane;
        int sv = (idx < end) ? g_csrc[idx] : 0;
        int cnt = min(32, end - t);
        for (int j = 0; j < cnt; j += 4) {
            int jj = j + grp;
            int s = __shfl_sync(0xffffffffu, sv, jj & 31);
            if (jj < cnt) {
                float4 a = *(const float4*)&g_h1s[s * 32 + cb];
                acc.x += a.x; acc.y += a.y; acc.z += a.z; acc.w += a.w;
            }
        }
    }
    // reduce across the 4 neighbor groups (lane bits 3,4)
#pragma unroll
    for (int m = 8; m <= 16; m <<= 1) {
        acc.x += __shfl_xor_sync(0xffffffffu, acc.x, m);
        acc.y += __shfl_xor_sync(0xffffffffu, acc.y, m);
        acc.z += __shfl_xor_sync(0xffffffffu, acc.z, m);
        acc.w += __shfl_xor_sync(0xffffffffu, acc.w, m);
    }
    // lanes 0..7 hold full col sums for cols cb..cb+3
    float dv = g_dinv[node];
    float4 root = *(const float4*)&g_root1[node * 32 + cb];
    float4 bv = *(const float4*)&bias1[cb];
    float4 r;
    r.x = fmaxf(dv * acc.x + root.x + bv.x, 0.f);
    r.y = fmaxf(dv * acc.y + root.y + bv.y, 0.f);
    r.z = fmaxf(dv * acc.z + root.z + bv.z, 0.f);
    r.w = fmaxf(dv * acc.w + root.w + bv.w, 0.f);
    // K-mean: col c pairs with c+16 -> lane pairs with lane^4
    float4 o;
    o.x = __shfl_xor_sync(0xffffffffu, r.x, 4);
    o.y = __shfl_xor_sync(0xffffffffu, r.y, 4);
    o.z = __shfl_xor_sync(0xffffffffu, r.z, 4);
    o.w = __shfl_xor_sync(0xffffffffu, r.w, 4);
    float4 h;
    h.x = 0.5f * (r.x + o.x);
    h.y = 0.5f * (r.y + o.y);
    h.z = 0.5f * (r.z + o.z);
    h.w = 0.5f * (r.w + o.w);
    if (lane < 4) {
        *(float4*)&out_agg[node * 16 + lane * 4] = h;   // agg_feature output
        float4 hs = make_float4(h.x * dv, h.y * dv, h.z * dv, h.w * dv);
        *(float4*)&g_hs[node * 16 + lane * 4] = hs;
    }
}

// ---------------- layer-2 aggregate ------------------------------------------
// warp per dst node; 4 lanes cover one 64B row; 8 neighbors in flight
__global__ void __launch_bounds__(256) k_agg2() {
    int node = blockIdx.x * 8 + (threadIdx.x >> 5);
    int lane = threadIdx.x & 31;
    if (node >= NN) return;
    int beg = g_off[node], end = g_off[node + 1];
    int grp = lane >> 2;       // 0..7
    int cb = (lane & 3) * 4;   // column base 0..12

    float4 acc = make_float4(0.f, 0.f, 0.f, 0.f);
    for (int t = beg; t < end; t += 32) {
        int idx = t + lane;
        int sv = (idx < end) ? g_csrc[idx] : 0;
        int cnt = min(32, end - t);
        for (int j = 0; j < cnt; j += 8) {
            int jj = j + grp;
            int s = __shfl_sync(0xffffffffu, sv, jj & 31);
            if (jj < cnt) {
                float4 a = *(const float4*)&g_hs[s * 16 + cb];
                acc.x += a.x; acc.y += a.y; acc.z += a.z; acc.w += a.w;
            }
        }
    }
#pragma unroll
    for (int m = 4; m <= 16; m <<= 1) {
        acc.x += __shfl_xor_sync(0xffffffffu, acc.x, m);
        acc.y += __shfl_xor_sync(0xffffffffu, acc.y, m);
        acc.z += __shfl_xor_sync(0xffffffffu, acc.z, m);
        acc.w += __shfl_xor_sync(0xffffffffu, acc.w, m);
    }
    if (lane < 4) {
        float dv = g_dinv[node];
        float4 v = make_float4(acc.x * dv, acc.y * dv, acc.z * dv, acc.w * dv);
        *(float4*)&g_aggh[node * 16 + lane * 4] = v;
    }
}

// ---------------- layer-2 transform + log_softmax ----------------------------
__global__ void __launch_bounds__(256) k_final(const float* __restrict__ wi2,
                                               const float* __restrict__ wr2,
                                               const float* __restrict__ b2,
                                               const float* __restrict__ hsrc,
                                               float* __restrict__ out_logits) {
    __shared__ float Wi[256], Wr[256], Ba[16];
    int t = threadIdx.x;
    // K-mean commutes with identity activation -> average weights over stacks
    Wi[t] = 0.5f * (wi2[t] + wi2[256 + t]);
    Wr[t] = 0.5f * (wr2[t] + wr2[256 + t]);
    if (t < 16) Ba[t] = 0.5f * (b2[t] + b2[16 + t]);
    __syncthreads();

    int n = blockIdx.x * 256 + t;
    if (n >= NN) return;
    float g[16], h[16];
#pragma unroll
    for (int j = 0; j < 4; j++) {
        float4 gv = *(const float4*)&g_aggh[n * 16 + j * 4];
        float4 hv = *(const float4*)&hsrc[n * 16 + j * 4];
        g[j * 4 + 0] = gv.x; g[j * 4 + 1] = gv.y; g[j * 4 + 2] = gv.z; g[j * 4 + 3] = gv.w;
        h[j * 4 + 0] = hv.x; h[j * 4 + 1] = hv.y; h[j * 4 + 2] = hv.z; h[j * 4 + 3] = hv.w;
    }
    float l[16];
    float m = -1e30f;
#pragma unroll
    for (int o = 0; o < 16; o++) {
        float a = Ba[o];
#pragma unroll
        for (int ff = 0; ff < 16; ff++)
            a += g[ff] * Wi[ff * 16 + o] + h[ff] * Wr[ff * 16 + o];
        l[o] = a;
        m = fmaxf(m, a);
    }
    float s = 0.f;
#pragma unroll
    for (int o = 0; o < 16; o++) s += expf(l[o] - m);
    float ls = logf(s);
#pragma unroll
    for (int j = 0; j < 4; j++) {
        float4 v;
        v.x = l[j * 4 + 0] - m - ls;
        v.y = l[j * 4 + 1] - m - ls;
        v.z = l[j * 4 + 2] - m - ls;
        v.w = l[j * 4 + 3] - m - ls;
        *(float4*)&out_logits[n * 16 + j * 4] = v;
    }
}

// ---------------- launch -----------------------------------------------------
extern "C" void kernel_launch(void* const* d_in, const int* in_sizes, int n_in,
                              void* d_out, int out_size) {
    const float* x   = (const float*)d_in[0];
    const int*   ei  = (const int*)d_in[1];     // int32 (JAX x64 disabled)
    const float* wi1 = (const float*)d_in[2];
    const float* wr1 = (const float*)d_in[3];
    const float* b1  = (const float*)d_in[4];
    const float* wi2 = (const float*)d_in[5];
    const float* wr2 = (const float*)d_in[6];
    const float* b2  = (const float*)d_in[7];
    float* out        = (float*)d_out;
    float* out_logits = out;            // [N, 16] log_softmax
    float* out_agg    = out + NN * 16;  // [N, 16] agg_feature

    bool dual = g_hx.ok;
    if (dual) cudaEventRecord(g_hx.ev_fork, 0);   // fork point

    // main stream: CSR build chain
    k_zero<<<(NN + 255) / 256, 256>>>();
    k_hist<<<(EE / 4 + 255) / 256, 256>>>(ei);
    k_scan_part<<<NB_SCAN, 256>>>();
    if (dual) cudaEventRecord(g_hx.ev_dinv, 0);   // dinv ready

    // s2: gemm1 (overlaps CSR chain), then dinv-scale of h1s
    if (dual) {
        cudaStreamWaitEvent(g_hx.s2, g_hx.ev_fork, 0);
        k_gemm1<<<(NN + 127) / 128, 256, 0, g_hx.s2>>>(x, wi1, wr1);  // 4th launch
        cudaStreamWaitEvent(g_hx.s2, g_hx.ev_dinv, 0);
        k_scale<<<(NN * 8 + 255) / 256, 256, 0, g_hx.s2>>>();
        cudaEventRecord(g_hx.ev_join, g_hx.s2);
    } else {
        k_gemm1<<<(NN + 127) / 128, 256>>>(x, wi1, wr1);
    }

    k_scan_top<<<1, 512>>>();
    k_scan_out<<<NB_SCAN, 256>>>();
    k_csr<<<(EE / 4 + 255) / 256, 256>>>(ei);

    if (dual) {
        cudaStreamWaitEvent(0, g_hx.ev_join, 0);  // join before agg1
    } else {
        k_scale<<<(NN * 8 + 255) / 256, 256>>>();
    }

    k_agg1<<<(NN + 7) / 8, 256>>>(b1, out_agg);
    k_agg2<<<(NN + 7) / 8, 256>>>();
    k_final<<<(NN + 255) / 256, 256>>>(wi2, wr2, b2, out_agg, out_logits);
}

// round 9
// speedup vs baseline: 1.2935x; 1.0569x over previous
#include <cuda_runtime.h>

#define NN  100000
#define EE  3200000
#define NB_SCAN 391   // ceil(NN/256)

// ---------------- scratch (static device globals) ---------------------------
__device__ int   g_degi[NN];
__device__ float g_dinv[NN];
__device__ int   g_off[NN + 1];
__device__ int   g_cur[NN];
__device__ int   g_csrc[EE];
__device__ float g_h1s[NN * 32];    // x@init_w1; after k_scale: dinv[n]*that
__device__ float g_root1[NN * 32];  // x[n] @ root_w1 (raw)
__device__ float g_hs[NN * 16];     // dinv[n] * h[n]
__device__ float g_aggh[NN * 16];   // dinv[d] * sum_src hs[src]
__device__ int   g_bsum[512];
__device__ int   g_boff[512];

// ---------------- streams/events (created at image load, before harness) ----
struct HxStreams {
    cudaStream_t s2 = nullptr;
    cudaEvent_t ev_fork = nullptr, ev_dinv = nullptr, ev_join = nullptr;
    bool ok = false;
    HxStreams() {
        ok = (cudaStreamCreateWithFlags(&s2, cudaStreamNonBlocking) == cudaSuccess) &&
             (cudaEventCreateWithFlags(&ev_fork, cudaEventDisableTiming) == cudaSuccess) &&
             (cudaEventCreateWithFlags(&ev_dinv, cudaEventDisableTiming) == cudaSuccess) &&
             (cudaEventCreateWithFlags(&ev_join, cudaEventDisableTiming) == cudaSuccess);
    }
};
static HxStreams g_hx;

// ---------------- packed f32x2 helpers ---------------------------------------
typedef unsigned long long u64;
__device__ __forceinline__ u64 ffma2(u64 a, u64 b, u64 c) {
    u64 d;
    asm("fma.rn.f32x2 %0, %1, %2, %3;" : "=l"(d) : "l"(a), "l"(b), "l"(c));
    return d;
}
__device__ __forceinline__ u64 pack2(float lo, float hi) {
    u64 r;
    asm("mov.b64 %0, {%1, %2};" : "=l"(r) : "f"(lo), "f"(hi));
    return r;
}
__device__ __forceinline__ void unpack2(u64 v, float& lo, float& hi) {
    asm("mov.b64 {%0, %1}, %2;" : "=f"(lo), "=f"(hi) : "l"(v));
}

// ---------------- K: zero degree histogram -----------------------------------
__global__ void k_zero() {
    int i = blockIdx.x * blockDim.x + threadIdx.x;
    if (i < NN) g_degi[i] = 0;
}

// ---------------- K: degree histogram (int32 dst, int4 vectorized) ----------
__global__ void k_hist(const int* __restrict__ ei) {
    int e4 = blockIdx.x * blockDim.x + threadIdx.x;
    if (e4 >= EE / 4) return;
    int4 d = *(const int4*)&ei[EE + e4 * 4];
    if ((unsigned)d.x < NN) atomicAdd(&g_degi[d.x], 1);
    if ((unsigned)d.y < NN) atomicAdd(&g_degi[d.y], 1);
    if ((unsigned)d.z < NN) atomicAdd(&g_degi[d.z], 1);
    if ((unsigned)d.w < NN) atomicAdd(&g_degi[d.w], 1);
}

// ---------------- scan partials + dinv ---------------------------------------
__global__ void k_scan_part() {
    __shared__ int sm[256];
    int t = threadIdx.x, b = blockIdx.x;
    int n = b * 256 + t;
    int v = (n < NN) ? g_degi[n] : 0;
    if (n < NN) g_dinv[n] = (v > 0) ? rsqrtf((float)v) : 0.0f;
    sm[t] = v;
    __syncthreads();
    for (int s = 128; s > 0; s >>= 1) {
        if (t < s) sm[t] += sm[t + s];
        __syncthreads();
    }
    if (t == 0) g_bsum[b] = sm[0];
}

__global__ void k_scan_top() {
    __shared__ int sm[512];
    int t = threadIdx.x;
    int v = (t < NB_SCAN) ? g_bsum[t] : 0;
    sm[t] = v;
    __syncthreads();
    for (int d = 1; d < 512; d <<= 1) {
        int x = (t >= d) ? sm[t - d] : 0;
        __syncthreads();
        sm[t] += x;
        __syncthreads();
    }
    if (t < NB_SCAN) g_boff[t] = sm[t] - v;  // exclusive
}

__global__ void k_scan_out() {
    __shared__ int sm[256];
    int t = threadIdx.x, b = blockIdx.x;
    int n = b * 256 + t;
    int v = (n < NN) ? g_degi[n] : 0;
    sm[t] = v;
    __syncthreads();
    for (int d = 1; d < 256; d <<= 1) {
        int x = (t >= d) ? sm[t - d] : 0;
        __syncthreads();
        sm[t] += x;
        __syncthreads();
    }
    int excl = sm[t] - v + g_boff[b];
    if (n < NN) {
        g_off[n] = excl;
        g_cur[n] = excl;
    }
    if (b == 0 && t == 0) g_off[NN] = EE;
}

// ---------------- GEMM1 (R4 champion variant, 86.4us measured) ---------------
// tile: 128 nodes x 64 outputs, 256 threads; thread = 8 rows x 4 cols (f32x2)
__global__ void __launch_bounds__(256) k_gemm1(const float* __restrict__ x,
                                               const float* __restrict__ wi,
                                               const float* __restrict__ wr) {
    __shared__ float xs[128 * 68];
    __shared__ float ws[64 * 64];
    int tid = threadIdx.x;
    int nb = blockIdx.x * 128;
    int co = tid & 15;   // output group: cols co*4 .. co*4+3
    int rn = tid >> 4;   // row group:    rows rn*8 .. rn*8+7

    u64 acc[8][2];
#pragma unroll
    for (int i = 0; i < 8; i++) { acc[i][0] = 0ull; acc[i][1] = 0ull; }

    for (int fc = 0; fc < 256; fc += 64) {
        // stage x tile [128 rows x 64 features], 8 float4/thread
#pragma unroll
        for (int j = 0; j < 8; j++) {
            int idx = tid + 256 * j;
            int r = idx >> 4;
            int c4 = (idx & 15) * 4;
            float4 v = make_float4(0.f, 0.f, 0.f, 0.f);
            int node = nb + r;
            if (node < NN) v = *(const float4*)&x[node * 256 + fc + c4];
            *(float4*)&xs[r * 68 + c4] = v;
        }
        // stage W tile [64 f x 64 outputs], 4 float4/thread
        // o layout: [wi k0 h0..15 | wi k1 h0..15 | wr k0 h0..15 | wr k1 h0..15]
#pragma unroll
        for (int j = 0; j < 4; j++) {
            int idx = tid + 256 * j;
            int fl = idx >> 4;
            int o4 = idx & 15;
            int m = o4 >> 2;      // 0..3
            int k = m & 1;
            int h4 = o4 & 3;
            const float* wp = (m < 2) ? wi : wr;
            float4 v = *(const float4*)&wp[k * 4096 + (fc + fl) * 16 + h4 * 4];
            *(float4*)&ws[fl * 64 + o4 * 4] = v;
        }
        __syncthreads();
#pragma unroll 8
        for (int f = 0; f < 64; f++) {
            float4 w = *(float4*)&ws[f * 64 + co * 4];
            u64 w01 = pack2(w.x, w.y);
            u64 w23 = pack2(w.z, w.w);
#pragma unroll
            for (int i = 0; i < 8; i++) {
                float xv = xs[(rn * 8 + i) * 68 + f];
                u64 xx = pack2(xv, xv);
                acc[i][0] = ffma2(xx, w01, acc[i][0]);
                acc[i][1] = ffma2(xx, w23, acc[i][1]);
            }
        }
        __syncthreads();
    }
    // epilogue (raw outputs; dinv applied later by k_scale)
#pragma unroll
    for (int i = 0; i < 8; i++) {
        int node = nb + rn * 8 + i;
        if (node >= NN) continue;
        float4 v;
        unpack2(acc[i][0], v.x, v.y);
        unpack2(acc[i][1], v.z, v.w);
        if (co < 8) {
            *(float4*)&g_h1s[node * 32 + co * 4] = v;
        } else {
            *(float4*)&g_root1[node * 32 + (co - 8) * 4] = v;
        }
    }
}

// ---------------- K: scale h1s rows by dinv (streaming, ~4us) ---------------
__global__ void k_scale() {
    int i = blockIdx.x * blockDim.x + threadIdx.x;   // over NN*8 float4s
    if (i >= NN * 8) return;
    int node = i >> 3;
    float dv = g_dinv[node];
    float4 v = *(float4*)&g_h1s[i * 4];
    v.x *= dv; v.y *= dv; v.z *= dv; v.w *= dv;
    *(float4*)&g_h1s[i * 4] = v;
}

// ---------------- CSR scatter (src grouped by dst), int4 vectorized ---------
__global__ void k_csr(const int* __restrict__ ei) {
    int e4 = blockIdx.x * blockDim.x + threadIdx.x;
    if (e4 >= EE / 4) return;
    int4 s = *(const int4*)&ei[e4 * 4];
    int4 d = *(const int4*)&ei[EE + e4 * 4];
    if ((unsigned)d.x < NN) g_csrc[atomicAdd(&g_cur[d.x], 1)] = s.x;
    if ((unsigned)d.y < NN) g_csrc[atomicAdd(&g_cur[d.y], 1)] = s.y;
    if ((unsigned)d.z < NN) g_csrc[atomicAdd(&g_cur[d.z], 1)] = s.z;
    if ((unsigned)d.w < NN) g_csrc[atomicAdd(&g_cur[d.w], 1)] = s.w;
}

// ---------------- layer-1 aggregate + combine --------------------------------
// warp per dst node; 4 groups x 8 lanes; group g handles neighbors
// beg+g, beg+g+4, ... (stride 4). No shfl: all 8 lanes of a group load the
// same g_csrc entry (hardware broadcast). Unroll x4 -> ~8 loads in flight.
__global__ void __launch_bounds__(256) k_agg1(const float* __restrict__ bias1,
                                              float* __restrict__ out_agg) {
    int node = blockIdx.x * 8 + (threadIdx.x >> 5);
    int lane = threadIdx.x & 31;
    if (node >= NN) return;
    int beg = g_off[node], end = g_off[node + 1];
    int grp = lane >> 3;       // 0..3
    int cb = (lane & 7) * 4;   // column base 0..28

    float4 acc = make_float4(0.f, 0.f, 0.f, 0.f);
    int t = beg + grp;
    for (; t + 12 < end; t += 16) {
        int s0 = g_csrc[t];
        int s1 = g_csrc[t + 4];
        int s2 = g_csrc[t + 8];
        int s3 = g_csrc[t + 12];
        float4 a0 = *(const float4*)&g_h1s[s0 * 32 + cb];
        float4 a1 = *(const float4*)&g_h1s[s1 * 32 + cb];
        float4 a2 = *(const float4*)&g_h1s[s2 * 32 + cb];
        float4 a3 = *(const float4*)&g_h1s[s3 * 32 + cb];
        acc.x += (a0.x + a1.x) + (a2.x + a3.x);
        acc.y += (a0.y + a1.y) + (a2.y + a3.y);
        acc.z += (a0.z + a1.z) + (a2.z + a3.z);
        acc.w += (a0.w + a1.w) + (a2.w + a3.w);
    }
    for (; t < end; t += 4) {
        int s = g_csrc[t];
        float4 a = *(const float4*)&g_h1s[s * 32 + cb];
        acc.x += a.x; acc.y += a.y; acc.z += a.z; acc.w += a.w;
    }
    // reduce across the 4 neighbor groups (lane bits 3,4)
#pragma unroll
    for (int m = 8; m <= 16; m <<= 1) {
        acc.x += __shfl_xor_sync(0xffffffffu, acc.x, m);
        acc.y += __shfl_xor_sync(0xffffffffu, acc.y, m);
        acc.z += __shfl_xor_sync(0xffffffffu, acc.z, m);
        acc.w += __shfl_xor_sync(0xffffffffu, acc.w, m);
    }
    // lanes 0..7 hold full col sums for cols cb..cb+3
    float dv = g_dinv[node];
    float4 root = *(const float4*)&g_root1[node * 32 + cb];
    float4 bv = *(const float4*)&bias1[cb];
    float4 r;
    r.x = fmaxf(dv * acc.x + root.x + bv.x, 0.f);
    r.y = fmaxf(dv * acc.y + root.y + bv.y, 0.f);
    r.z = fmaxf(dv * acc.z + root.z + bv.z, 0.f);
    r.w = fmaxf(dv * acc.w + root.w + bv.w, 0.f);
    // K-mean: col c pairs with c+16 -> lane pairs with lane^4
    float4 o;
    o.x = __shfl_xor_sync(0xffffffffu, r.x, 4);
    o.y = __shfl_xor_sync(0xffffffffu, r.y, 4);
    o.z = __shfl_xor_sync(0xffffffffu, r.z, 4);
    o.w = __shfl_xor_sync(0xffffffffu, r.w, 4);
    float4 h;
    h.x = 0.5f * (r.x + o.x);
    h.y = 0.5f * (r.y + o.y);
    h.z = 0.5f * (r.z + o.z);
    h.w = 0.5f * (r.w + o.w);
    if (lane < 4) {
        *(float4*)&out_agg[node * 16 + lane * 4] = h;   // agg_feature output
        float4 hs = make_float4(h.x * dv, h.y * dv, h.z * dv, h.w * dv);
        *(float4*)&g_hs[node * 16 + lane * 4] = hs;
    }
}

// ---------------- layer-2 aggregate ------------------------------------------
// warp per dst node; 8 groups x 4 lanes; group g: neighbors beg+g, +8, ...
__global__ void __launch_bounds__(256) k_agg2() {
    int node = blockIdx.x * 8 + (threadIdx.x >> 5);
    int lane = threadIdx.x & 31;
    if (node >= NN) return;
    int beg = g_off[node], end = g_off[node + 1];
    int grp = lane >> 2;       // 0..7
    int cb = (lane & 3) * 4;   // column base 0..12

    float4 acc = make_float4(0.f, 0.f, 0.f, 0.f);
    int t = beg + grp;
    for (; t + 24 < end; t += 32) {
        int s0 = g_csrc[t];
        int s1 = g_csrc[t + 8];
        int s2 = g_csrc[t + 16];
        int s3 = g_csrc[t + 24];
        float4 a0 = *(const float4*)&g_hs[s0 * 16 + cb];
        float4 a1 = *(const float4*)&g_hs[s1 * 16 + cb];
        float4 a2 = *(const float4*)&g_hs[s2 * 16 + cb];
        float4 a3 = *(const float4*)&g_hs[s3 * 16 + cb];
        acc.x += (a0.x + a1.x) + (a2.x + a3.x);
        acc.y += (a0.y + a1.y) + (a2.y + a3.y);
        acc.z += (a0.z + a1.z) + (a2.z + a3.z);
        acc.w += (a0.w + a1.w) + (a2.w + a3.w);
    }
    for (; t < end; t += 8) {
        int s = g_csrc[t];
        float4 a = *(const float4*)&g_hs[s * 16 + cb];
        acc.x += a.x; acc.y += a.y; acc.z += a.z; acc.w += a.w;
    }
#pragma unroll
    for (int m = 4; m <= 16; m <<= 1) {
        acc.x += __shfl_xor_sync(0xffffffffu, acc.x, m);
        acc.y += __shfl_xor_sync(0xffffffffu, acc.y, m);
        acc.z += __shfl_xor_sync(0xffffffffu, acc.z, m);
        acc.w += __shfl_xor_sync(0xffffffffu, acc.w, m);
    }
    if (lane < 4) {
        float dv = g_dinv[node];
        float4 v = make_float4(acc.x * dv, acc.y * dv, acc.z * dv, acc.w * dv);
        *(float4*)&g_aggh[node * 16 + lane * 4] = v;
    }
}

// ---------------- layer-2 transform + log_softmax ----------------------------
__global__ void __launch_bounds__(256) k_final(const float* __restrict__ wi2,
                                               const float* __restrict__ wr2,
                                               const float* __restrict__ b2,
                                               const float* __restrict__ hsrc,
                                               float* __restrict__ out_logits) {
    __shared__ float Wi[256], Wr[256], Ba[16];
    int t = threadIdx.x;
    // K-mean commutes with identity activation -> average weights over stacks
    Wi[t] = 0.5f * (wi2[t] + wi2[256 + t]);
    Wr[t] = 0.5f * (wr2[t] + wr2[256 + t]);
    if (t < 16) Ba[t] = 0.5f * (b2[t] + b2[16 + t]);
    __syncthreads();

    int n = blockIdx.x * 256 + t;
    if (n >= NN) return;
    float g[16], h[16];
#pragma unroll
    for (int j = 0; j < 4; j++) {
        float4 gv = *(const float4*)&g_aggh[n * 16 + j * 4];
        float4 hv = *(const float4*)&hsrc[n * 16 + j * 4];
        g[j * 4 + 0] = gv.x; g[j * 4 + 1] = gv.y; g[j * 4 + 2] = gv.z; g[j * 4 + 3] = gv.w;
        h[j * 4 + 0] = hv.x; h[j * 4 + 1] = hv.y; h[j * 4 + 2] = hv.z; h[j * 4 + 3] = hv.w;
    }
    float l[16];
    float m = -1e30f;
#pragma unroll
    for (int o = 0; o < 16; o++) {
        float a = Ba[o];
#pragma unroll
        for (int ff = 0; ff < 16; ff++)
            a += g[ff] * Wi[ff * 16 + o] + h[ff] * Wr[ff * 16 + o];
        l[o] = a;
        m = fmaxf(m, a);
    }
    float s = 0.f;
#pragma unroll
    for (int o = 0; o < 16; o++) s += expf(l[o] - m);
    float ls = logf(s);
#pragma unroll
    for (int j = 0; j < 4; j++) {
        float4 v;
        v.x = l[j * 4 + 0] - m - ls;
        v.y = l[j * 4 + 1] - m - ls;
        v.z = l[j * 4 + 2] - m - ls;
        v.w = l[j * 4 + 3] - m - ls;
        *(float4*)&out_logits[n * 16 + j * 4] = v;
    }
}

// ---------------- launch -----------------------------------------------------
extern "C" void kernel_launch(void* const* d_in, const int* in_sizes, int n_in,
                              void* d_out, int out_size) {
    const float* x   = (const float*)d_in[0];
    const int*   ei  = (const int*)d_in[1];     // int32 (JAX x64 disabled)
    const float* wi1 = (const float*)d_in[2];
    const float* wr1 = (const float*)d_in[3];
    const float* b1  = (const float*)d_in[4];
    const float* wi2 = (const float*)d_in[5];
    const float* wr2 = (const float*)d_in[6];
    const float* b2  = (const float*)d_in[7];
    float* out        = (float*)d_out;
    float* out_logits = out;            // [N, 16] log_softmax
    float* out_agg    = out + NN * 16;  // [N, 16] agg_feature

    bool dual = g_hx.ok;
    if (dual) cudaEventRecord(g_hx.ev_fork, 0);   // fork point

    // main stream: CSR build chain
    k_zero<<<(NN + 255) / 256, 256>>>();
    k_hist<<<(EE / 4 + 255) / 256, 256>>>(ei);
    k_scan_part<<<NB_SCAN, 256>>>();
    if (dual) cudaEventRecord(g_hx.ev_dinv, 0);   // dinv ready

    // s2: gemm1 (overlaps CSR chain), then dinv-scale of h1s
    if (dual) {
        cudaStreamWaitEvent(g_hx.s2, g_hx.ev_fork, 0);
        k_gemm1<<<(NN + 127) / 128, 256, 0, g_hx.s2>>>(x, wi1, wr1);  // 4th launch
        cudaStreamWaitEvent(g_hx.s2, g_hx.ev_dinv, 0);
        k_scale<<<(NN * 8 + 255) / 256, 256, 0, g_hx.s2>>>();
        cudaEventRecord(g_hx.ev_join, g_hx.s2);
    } else {
        k_gemm1<<<(NN + 127) / 128, 256>>>(x, wi1, wr1);
    }

    k_scan_top<<<1, 512>>>();
    k_scan_out<<<NB_SCAN, 256>>>();
    k_csr<<<(EE / 4 + 255) / 256, 256>>>(ei);

    if (dual) {
        cudaStreamWaitEvent(0, g_hx.ev_join, 0);  // join before agg1
    } else {
        k_scale<<<(NN * 8 + 255) / 256, 256>>>();
    }

    k_agg1<<<(NN + 7) / 8, 256>>>(b1, out_agg);
    k_agg2<<<(NN + 7) / 8, 256>>>();
    k_final<<<(NN + 255) / 256, 256>>>(wi2, wr2, b2, out_agg, out_logits);
}